// round 11
// baseline (speedup 1.0000x reference)
#include <cuda_runtime.h>
#include <cfloat>
#include <climits>
#include <math.h>

#define NPTS     4096
#define G_TOTAL  65536
#define NBUCK    64            // y-strips (global) and x-buckets (smem)
#define INV_CELL (1.0f / 16.0f)
#define NEG_INF_F (__int_as_float(0xff800000))

#define MAIN_T   256
#define NBLK     (G_TOTAL / MAIN_T)   // 256 blocks, all co-resident
#define NSUB     4                    // sub-builders per strip (NBLK = NBUCK*NSUB)
#define SCAP     NPTS                 // strip capacity: overflow impossible
#define CAPB     16                   // per-x-bucket capacity
#define OCAP     64                   // x overflow list capacity
#define PAD      0.25f                // covers reference d2 rounding slack
#define BAIL     (1 << 16)            // poll bound -> full-scan fallback

// Global strip index + sync (static scratch — no allocation)
__device__ float4 g_strip[NBUCK][SCAP];   // x, y, p2, score
__device__ int    g_spid [NBUCK][SCAP];   // original point index
__device__ int    g_scnt [NBUCK];         // per-strip count (global atomic)
__device__ int    g_done [NBUCK];         // sub-builders finished (0..NSUB)

// Lexicographic (d, pid) top-4 insertion — exactly matches top_k tie-breaking.
__device__ __forceinline__ void insert4(
    float d, int pid, float sc,
    float& da, float& db, float& dc, float& dd,
    int& ia, int& ib, int& ic, int& id_,
    float& sa, float& sb, float& sc_, float& sd)
{
    if (d < dd || (d == dd && pid < id_)) {
        dd = d; id_ = pid; sd = sc;
        if (dd < dc || (dd == dc && id_ < ic)) {
            float td = dc; int ti = ic; float ts = sc_;
            dc = dd; ic = id_; sc_ = sd;
            dd = td; id_ = ti; sd = ts;
            if (dc < db || (dc == db && ic < ib)) {
                td = db; ti = ib; ts = sb;
                db = dc; ib = ic; sb = sc_;
                dc = td; ic = ti; sc_ = ts;
                if (db < da || (db == da && ib < ia)) {
                    td = da; ti = ia; ts = sa;
                    da = db; ia = ib; sa = sb;
                    db = td; ib = ti; sb = ts;
                }
            }
        }
    }
}

// ---------------------------------------------------------------------------
// One kernel, 256 blocks x 256 threads, all co-resident.
// Every block: (1) builds 1/4 of one y-strip into global scratch and releases
// it via fence+done-counter, (2) waits for its own 2-3 strips, (3) gathers
// them into smem x-buckets, (4) per-thread windowed top-4 + filter + select.
// ---------------------------------------------------------------------------
__global__ void __launch_bounds__(MAIN_T, 4) pump_pipe_kernel(
    const float4* __restrict__ pos,      // (NPTS, 4)
    const float*  __restrict__ scores,   // (NPTS,)
    const float2* __restrict__ grid,     // (G, 2)
    const float*  __restrict__ accu,     // (G, 6)
    const float*  __restrict__ scale_p,
    const float*  __restrict__ code_p,
    float*        __restrict__ out)      // (G, 6)
{
    __shared__ float4 s_buck[NBUCK * CAPB];
    __shared__ int    s_bpid[NBUCK * CAPB];
    __shared__ int    s_cnt[NBUCK];
    __shared__ float4 s_ovf[OCAP];
    __shared__ int    s_opid[OCAP];
    __shared__ int    s_ocnt, s_fb;
    __shared__ float  s_wmin[MAIN_T / 32], s_wmax[MAIN_T / 32];

    const int tid = threadIdx.x;
    const int lane = tid & 31;
    const int warp = tid >> 5;
    const int g = blockIdx.x * MAIN_T + tid;

    // ---- front batch: independent gmem loads (consumer inputs + build slice)
    const float scale = __ldg(scale_p);
    const float code  = __ldg(code_p);
    const float2 gp = grid[g];
    const float gx = gp.x, gy = gp.y;

    const float2* acc2 = (const float2*)accu;
    const float2 a01 = acc2[g * 3 + 0];
    const float2 a23 = acc2[g * 3 + 1];
    const float2 a45 = acc2[g * 3 + 2];

    const int bstrip = blockIdx.x >> 2;            // strip this block builds
    const int bsub   = blockIdx.x & (NSUB - 1);    // which quarter of points
    const int bbase  = bsub * (NPTS / NSUB);       // 1024-point slice

    float4 pb[NPTS / NSUB / MAIN_T];               // 4 points per thread
    float  sb_[NPTS / NSUB / MAIN_T];
    #pragma unroll
    for (int i = 0; i < NPTS / NSUB / MAIN_T; i++) {
        const int idx = bbase + tid + i * MAIN_T;
        pb[i]  = pos[idx];
        sb_[i] = __ldg(&scores[idx]);
    }

    const float g2 = __fadd_rn(__fmul_rn(gx, gx), __fmul_rn(gy, gy));
    const float dist_max = __fsub_rn(__fmul_rn(8.0f, scale), 1e-7f);
    const float rp = dist_max + PAD;

    // ---- init smem + per-warp y-range, one barrier ----
    if (tid < NBUCK) s_cnt[tid] = 0;
    if (tid == 0) { s_ocnt = 0; s_fb = 0; }
    {
        float lo = gy, hi = gy;
        #pragma unroll
        for (int o = 16; o > 0; o >>= 1) {
            lo = fminf(lo, __shfl_xor_sync(0xffffffffu, lo, o));
            hi = fmaxf(hi, __shfl_xor_sync(0xffffffffu, hi, o));
        }
        if (lane == 0) { s_wmin[warp] = lo; s_wmax[warp] = hi; }
    }
    __syncthreads();

    // ---- build: scatter this slice's strip-bstrip points to global ----
    #pragma unroll
    for (int i = 0; i < NPTS / NSUB / MAIN_T; i++) {
        const float4 p = pb[i];
        int st = (int)floorf(p.y * INV_CELL);
        st = min(NBUCK - 1, max(0, st));
        if (st == bstrip) {
            const int slot = atomicAdd(&g_scnt[bstrip], 1);
            const float p2 = __fadd_rn(__fmul_rn(p.x, p.x), __fmul_rn(p.y, p.y));
            g_strip[bstrip][slot] = make_float4(p.x, p.y, p2, sb_[i]);
            g_spid [bstrip][slot] = bbase + tid + i * MAIN_T;
        }
    }
    __threadfence();               // release: data visible before done++
    __syncthreads();
    if (tid == 0) atomicAdd(&g_done[bstrip], 1);

    // ---- consumer: which strips does this block need? ----
    float blo = s_wmin[0], bhi = s_wmax[0];
    #pragma unroll
    for (int w = 1; w < MAIN_T / 32; w++) {
        blo = fminf(blo, s_wmin[w]);
        bhi = fmaxf(bhi, s_wmax[w]);
    }
    const float ylo = blo - rp;
    const float yhi = bhi + rp;
    int s0 = (int)floorf(ylo * INV_CELL);
    int s1 = (int)floorf(yhi * INV_CELL);
    s0 = min(NBUCK - 1, max(0, s0));
    s1 = min(NBUCK - 1, max(0, s1));

    // ---- wait for needed strips (bounded; bail -> full-scan fallback) ----
    for (int s = s0 + tid; s <= s1; s += MAIN_T) {
        int it = 0;
        while (atomicAdd(&g_done[s], 0) < NSUB) {
            if (++it > BAIL) { s_fb = 1; break; }
            __nanosleep(128);
        }
    }
    __threadfence();               // acquire side
    __syncthreads();

    // ---- gather strips into smem x-buckets ----
    if (!s_fb) {
        for (int s = s0; s <= s1; s++) {
            const int cnt = min(__ldcg(&g_scnt[s]), SCAP);
            for (int k = tid; k < cnt; k += MAIN_T) {
                const float4 e = __ldcg(&g_strip[s][k]);
                const int pid = __ldcg(&g_spid[s][k]);
                int bx = (int)floorf(e.x * INV_CELL);
                bx = min(NBUCK - 1, max(0, bx));
                const int slot = atomicAdd(&s_cnt[bx], 1);
                if (slot < CAPB) {
                    s_buck[bx * CAPB + slot] = e;
                    s_bpid[bx * CAPB + slot] = pid;
                } else {
                    const int o = atomicAdd(&s_ocnt, 1);
                    if (o < OCAP) { s_ovf[o] = e; s_opid[o] = pid; }
                    else s_fb = 1;
                }
            }
        }
    }
    __syncthreads();
    const int fb = s_fb;

    // ---- phase B: top-4 by (d, pid) over the padded x-window ----
    float da = FLT_MAX, db = FLT_MAX, dc = FLT_MAX, dd = FLT_MAX;
    int   ia = INT_MAX, ib = INT_MAX, ic = INT_MAX, id_ = INT_MAX;
    float sa = 0.0f,    sbv = 0.0f,   sc_ = 0.0f,   sd = 0.0f;

    if (!fb) {
        int bx0 = (int)floorf((gx - rp) * INV_CELL);
        int bx1 = (int)floorf((gx + rp) * INV_CELL);
        bx0 = min(NBUCK - 1, max(0, bx0));
        bx1 = min(NBUCK - 1, max(0, bx1));

        for (int bx = bx0; bx <= bx1; bx++) {
            const int n = min(s_cnt[bx], CAPB);
            const int base = bx * CAPB;
            for (int k = 0; k < n; k++) {
                const float4 e = s_buck[base + k];
                const int pid = s_bpid[base + k];
                const float dot = __fmaf_rn(e.y, gy, __fmul_rn(e.x, gx));
                const float d2 = __fsub_rn(__fadd_rn(e.z, g2),
                                           __fmul_rn(2.0f, dot));
                const float d = sqrtf(fmaxf(d2, 1e-12f));
                insert4(d, pid, e.w, da, db, dc, dd, ia, ib, ic, id_,
                        sa, sbv, sc_, sd);
            }
        }
        const int on = min(s_ocnt, OCAP);
        for (int k = 0; k < on; k++) {
            const float4 e = s_ovf[k];
            const int pid = s_opid[k];
            const float dot = __fmaf_rn(e.y, gy, __fmul_rn(e.x, gx));
            const float d2 = __fsub_rn(__fadd_rn(e.z, g2),
                                       __fmul_rn(2.0f, dot));
            const float d = sqrtf(fmaxf(d2, 1e-12f));
            insert4(d, pid, e.w, da, db, dc, dd, ia, ib, ic, id_,
                    sa, sbv, sc_, sd);
        }
    } else {
        // Fallback: scan everything from gmem (correct for any input).
        for (int idx = 0; idx < NPTS; idx++) {
            const float4 p = pos[idx];
            const float p2 = __fadd_rn(__fmul_rn(p.x, p.x), __fmul_rn(p.y, p.y));
            const float scv = scores[idx];
            const float dot = __fmaf_rn(p.y, gy, __fmul_rn(p.x, gx));
            const float d2 = __fsub_rn(__fadd_rn(p2, g2),
                                       __fmul_rn(2.0f, dot));
            const float d = sqrtf(fmaxf(d2, 1e-12f));
            insert4(d, idx, scv, da, db, dc, dd, ia, ib, ic, id_,
                    sa, sbv, sc_, sd);
        }
    }

    // ---- finalize: filter (d <= 2*d0) & (d < dist_max); max score,
    //      first occurrence wins ties (strict >) ----
    const float thr = __fmul_rn(2.0f, da);   // exact (power of 2)

    float best = NEG_INF_F;
    int bestid = 0;
    if (da <= thr && da < dist_max && sa  > best) { best = sa;  bestid = ia; }
    if (db <= thr && db < dist_max && sbv > best) { best = sbv; bestid = ib; }
    if (dc <= thr && dc < dist_max && sc_ > best) { best = sc_; bestid = ic; }
    if (dd <= thr && dd < dist_max && sd  > best) { best = sd;  bestid = id_; }

    float2* out2 = (float2*)out;
    if (best > a45.x) {
        const float4 pr = pos[bestid];
        out2[g * 3 + 0] = make_float2(pr.x, pr.y);
        out2[g * 3 + 1] = make_float2(pr.z, pr.w);
        out2[g * 3 + 2] = make_float2(best, code);
    } else {
        out2[g * 3 + 0] = a01;
        out2[g * 3 + 1] = a23;
        out2[g * 3 + 2] = a45;
    }
}

// ---------------------------------------------------------------------------
// Inputs (metadata order): pos (4096,4) f32, scores (4096,) f32,
// grid (65536,2) f32, accu (65536,6) f32, scale () f32, code () f32.
// ---------------------------------------------------------------------------
extern "C" void kernel_launch(void* const* d_in, const int* in_sizes, int n_in,
                              void* d_out, int out_size)
{
    const float4* pos    = (const float4*)d_in[0];
    const float*  scores = (const float*) d_in[1];
    const float2* grid   = (const float2*)d_in[2];
    const float*  accu   = (const float*) d_in[3];
    const float*  scale  = (const float*) d_in[4];
    const float*  code   = (const float*) d_in[5];
    float* out = (float*)d_out;

    // Reset pipeline sync state each launch (graph-capturable, no allocation).
    void* p_done = nullptr; void* p_scnt = nullptr;
    cudaGetSymbolAddress(&p_done, g_done);
    cudaGetSymbolAddress(&p_scnt, g_scnt);
    cudaMemsetAsync(p_done, 0, NBUCK * sizeof(int));
    cudaMemsetAsync(p_scnt, 0, NBUCK * sizeof(int));

    pump_pipe_kernel<<<NBLK, MAIN_T>>>(pos, scores, grid, accu,
                                       scale, code, out);
}

// round 12
// speedup vs baseline: 1.9077x; 1.9077x over previous
#include <cuda_runtime.h>
#include <cfloat>
#include <climits>
#include <math.h>

#define NPTS     4096
#define G_TOTAL  65536
#define NBUCK    64
#define INV_CELL (1.0f / 16.0f)
#define NEG_INF_F (__int_as_float(0xff800000))

#define BLOCK_T  512    // threads per block == grid points per block
#define GPTS     512    // 2 grid rows per block
#define NBLK     (G_TOTAL / GPTS)   // 128 blocks -> single wave, all resident
#define CAPB     16     // per-x-bucket capacity
#define OCAP     64     // x overflow list capacity
#define PAD      0.25f  // covers reference d2 rounding slack

// Lexicographic (d, pid) top-4 insertion — exactly matches top_k tie-breaking.
__device__ __forceinline__ void insert4(
    float d, int pid, float sc,
    float& da, float& db, float& dc, float& dd,
    int& ia, int& ib, int& ic, int& id_,
    float& sa, float& sb, float& sc_, float& sd)
{
    if (d < dd || (d == dd && pid < id_)) {
        dd = d; id_ = pid; sd = sc;
        if (dd < dc || (dd == dc && id_ < ic)) {
            float td = dc; int ti = ic; float ts = sc_;
            dc = dd; ic = id_; sc_ = sd;
            dd = td; id_ = ti; sd = ts;
            if (dc < db || (dc == db && ic < ib)) {
                td = db; ti = ib; ts = sb;
                db = dc; ib = ic; sb = sc_;
                dc = td; ic = ti; sc_ = ts;
                if (db < da || (db == da && ib < ia)) {
                    td = da; ti = ia; ts = sa;
                    da = db; ia = ib; sa = sb;
                    db = td; ib = ti; sb = ts;
                }
            }
        }
    }
}

// ---------------------------------------------------------------------------
// 128 blocks x 512 threads, single wave, 2 grid rows per block, one thread
// per grid point. Front batch: grid/accu/scale/code + pos.xy (float2 x8) +
// scores (x8), all independent, before the single pre-phase-A barrier.
// Phase A: bin y-strip survivors into smem x-buckets (all 512 threads).
// Phase B: each thread walks its 2-3 bucket window (few candidates).
// ---------------------------------------------------------------------------
__global__ void __launch_bounds__(BLOCK_T, 2) pump_fused_kernel(
    const float4* __restrict__ pos,      // (NPTS, 4)
    const float*  __restrict__ scores,   // (NPTS,)
    const float2* __restrict__ grid,     // (G, 2)
    const float*  __restrict__ accu,     // (G, 6)
    const float*  __restrict__ scale_p,
    const float*  __restrict__ code_p,
    float*        __restrict__ out)      // (G, 6)
{
    __shared__ float4 s_buck[NBUCK * CAPB];
    __shared__ int    s_bpid[NBUCK * CAPB];
    __shared__ int    s_cnt[NBUCK];
    __shared__ float4 s_ovf[OCAP];
    __shared__ int    s_opid[OCAP];
    __shared__ int    s_ocnt, s_fb;
    __shared__ float  s_wmin[BLOCK_T / 32], s_wmax[BLOCK_T / 32];

    const int tid = threadIdx.x;
    const int lane = tid & 31;
    const int warp = tid >> 5;
    const int g = blockIdx.x * GPTS + tid;

    // ---- front batch: every independent gmem load ----
    const float scale = __ldg(scale_p);
    const float code  = __ldg(code_p);
    const float2 gp = grid[g];
    const float gx = gp.x, gy = gp.y;

    const float2* acc2 = (const float2*)accu;
    const float2 a01 = acc2[g * 3 + 0];
    const float2 a23 = acc2[g * 3 + 1];
    const float2 a45 = acc2[g * 3 + 2];

    // pos.xy only (stride-16 float2): half the LDGs/registers of float4.
    const float2* pos2 = (const float2*)pos;
    float2 pxy[NPTS / BLOCK_T];
    float  sbuf[NPTS / BLOCK_T];
    #pragma unroll
    for (int i = 0; i < NPTS / BLOCK_T; i++) {
        const int idx = tid + i * BLOCK_T;
        pxy[i]  = pos2[idx * 2];          // (x, y) of point idx
        sbuf[i] = __ldg(&scores[idx]);
    }

    const float g2 = __fadd_rn(__fmul_rn(gx, gx), __fmul_rn(gy, gy));
    const float dist_max = __fsub_rn(__fmul_rn(8.0f, scale), 1e-7f);
    const float rp = dist_max + PAD;      // padded window radius

    // ---- init + per-warp y-range, ONE barrier ----
    if (tid < NBUCK) s_cnt[tid] = 0;
    if (tid == 0) { s_ocnt = 0; s_fb = 0; }
    {
        float lo = gy, hi = gy;
        #pragma unroll
        for (int o = 16; o > 0; o >>= 1) {
            lo = fminf(lo, __shfl_xor_sync(0xffffffffu, lo, o));
            hi = fmaxf(hi, __shfl_xor_sync(0xffffffffu, hi, o));
        }
        if (lane == 0) { s_wmin[warp] = lo; s_wmax[warp] = hi; }
    }
    __syncthreads();

    float blo = s_wmin[0], bhi = s_wmax[0];
    #pragma unroll
    for (int w = 1; w < BLOCK_T / 32; w++) {
        blo = fminf(blo, s_wmin[w]);
        bhi = fmaxf(bhi, s_wmax[w]);
    }
    const float ylo = blo - rp;
    const float yhi = bhi + rp;

    // ---- Phase A: bin survivors (from registers) into x-buckets ----
    #pragma unroll
    for (int i = 0; i < NPTS / BLOCK_T; i++) {
        const float px = pxy[i].x, py = pxy[i].y;
        if (py > ylo && py < yhi) {
            const int idx = tid + i * BLOCK_T;
            int bx = (int)floorf(px * INV_CELL);
            bx = min(NBUCK - 1, max(0, bx));
            const int slot = atomicAdd(&s_cnt[bx], 1);
            // reference rounding: round(x*x) + round(y*y)
            const float p2 = __fadd_rn(__fmul_rn(px, px), __fmul_rn(py, py));
            const float4 e = make_float4(px, py, p2, sbuf[i]);
            if (slot < CAPB) {
                s_buck[bx * CAPB + slot] = e;
                s_bpid[bx * CAPB + slot] = idx;
            } else {
                const int o = atomicAdd(&s_ocnt, 1);
                if (o < OCAP) { s_ovf[o] = e; s_opid[o] = idx; }
                else s_fb = 1;   // pathological input: full-scan fallback
            }
        }
    }
    __syncthreads();

    // ---- Phase B: top-4 by (d, pid) over the padded x-window ----
    float da = FLT_MAX, db = FLT_MAX, dc = FLT_MAX, dd = FLT_MAX;
    int   ia = INT_MAX, ib = INT_MAX, ic = INT_MAX, id_ = INT_MAX;
    float sa = 0.0f,    sb = 0.0f,    sc_ = 0.0f,   sd = 0.0f;

    if (!s_fb) {
        int bx0 = (int)floorf((gx - rp) * INV_CELL);
        int bx1 = (int)floorf((gx + rp) * INV_CELL);
        bx0 = min(NBUCK - 1, max(0, bx0));
        bx1 = min(NBUCK - 1, max(0, bx1));

        for (int bx = bx0; bx <= bx1; bx++) {
            const int n = min(s_cnt[bx], CAPB);
            const int base = bx * CAPB;
            for (int k = 0; k < n; k++) {
                const float4 e = s_buck[base + k];
                const int pid = s_bpid[base + k];
                const float dot = __fmaf_rn(e.y, gy, __fmul_rn(e.x, gx));
                const float d2 = __fsub_rn(__fadd_rn(e.z, g2),
                                           __fmul_rn(2.0f, dot));
                const float d = sqrtf(fmaxf(d2, 1e-12f));
                insert4(d, pid, e.w, da, db, dc, dd, ia, ib, ic, id_,
                        sa, sb, sc_, sd);
            }
        }
        const int on = min(s_ocnt, OCAP);
        for (int k = 0; k < on; k++) {
            const float4 e = s_ovf[k];
            const int pid = s_opid[k];
            const float dot = __fmaf_rn(e.y, gy, __fmul_rn(e.x, gx));
            const float d2 = __fsub_rn(__fadd_rn(e.z, g2),
                                       __fmul_rn(2.0f, dot));
            const float d = sqrtf(fmaxf(d2, 1e-12f));
            insert4(d, pid, e.w, da, db, dc, dd, ia, ib, ic, id_,
                    sa, sb, sc_, sd);
        }
    } else {
        // Fallback: scan everything from gmem (correct for any input).
        for (int idx = 0; idx < NPTS; idx++) {
            const float4 p = pos[idx];
            const float p2 = __fadd_rn(__fmul_rn(p.x, p.x), __fmul_rn(p.y, p.y));
            const float scv = scores[idx];
            const float dot = __fmaf_rn(p.y, gy, __fmul_rn(p.x, gx));
            const float d2 = __fsub_rn(__fadd_rn(p2, g2),
                                       __fmul_rn(2.0f, dot));
            const float d = sqrtf(fmaxf(d2, 1e-12f));
            insert4(d, idx, scv, da, db, dc, dd, ia, ib, ic, id_,
                    sa, sb, sc_, sd);
        }
    }

    // ---- Finalize: filter (d <= 2*d0) & (d < dist_max); max score,
    //      first occurrence wins ties (strict >) ----
    const float thr = __fmul_rn(2.0f, da);   // exact (power of 2)

    float best = NEG_INF_F;
    int bestid = 0;
    if (da <= thr && da < dist_max && sa  > best) { best = sa;  bestid = ia; }
    if (db <= thr && db < dist_max && sb  > best) { best = sb;  bestid = ib; }
    if (dc <= thr && dc < dist_max && sc_ > best) { best = sc_; bestid = ic; }
    if (dd <= thr && dd < dist_max && sd  > best) { best = sd;  bestid = id_; }

    float2* out2 = (float2*)out;
    if (best > a45.x) {
        const float4 pr = pos[bestid];
        out2[g * 3 + 0] = make_float2(pr.x, pr.y);
        out2[g * 3 + 1] = make_float2(pr.z, pr.w);
        out2[g * 3 + 2] = make_float2(best, code);
    } else {
        out2[g * 3 + 0] = a01;
        out2[g * 3 + 1] = a23;
        out2[g * 3 + 2] = a45;
    }
}

// ---------------------------------------------------------------------------
// Inputs (metadata order): pos (4096,4) f32, scores (4096,) f32,
// grid (65536,2) f32, accu (65536,6) f32, scale () f32, code () f32.
// ---------------------------------------------------------------------------
extern "C" void kernel_launch(void* const* d_in, const int* in_sizes, int n_in,
                              void* d_out, int out_size)
{
    const float4* pos    = (const float4*)d_in[0];
    const float*  scores = (const float*) d_in[1];
    const float2* grid   = (const float2*)d_in[2];
    const float*  accu   = (const float*) d_in[3];
    const float*  scale  = (const float*) d_in[4];
    const float*  code   = (const float*) d_in[5];
    float* out = (float*)d_out;

    pump_fused_kernel<<<NBLK, BLOCK_T>>>(pos, scores, grid, accu,
                                         scale, code, out);
}